// round 14
// baseline (speedup 1.0000x reference)
#include <cuda_runtime.h>
#include <cuda_fp16.h>
#include <cstdint>

#define B_DIM 128
#define E_DIM 512
#define H_DIM 1024
#define S_DIM 514
#define M_ROWS 65536
#define NEG_V (-1000000.0f)

// ---------------- device scratch ----------------
__device__ __half g_keys[(size_t)M_ROWS * H_DIM];  // keys in fp16
__device__ __half g_W1T[H_DIM * H_DIM];            // W1_bot^T [n][k] fp16
__device__ float g_basep[8 * B_DIM * H_DIM];       // k-split partials of q@W1_top
__device__ float g_nullrow[H_DIM];
__device__ float g_newrow[H_DIM];
__device__ float g_partial[4 * M_ROWS];

// ---------------- helpers ----------------
__device__ __forceinline__ uint32_t pack2h(float a, float b) {
    __half2 h = __floats2half2_rn(a, b);
    return reinterpret_cast<uint32_t&>(h);
}
__device__ __forceinline__ float gelu_exact(float x) {
    return 0.5f * x * (1.0f + erff(x * 0.70710678118654752f));
}
__device__ __forceinline__ float gelu_fast(float x) {
    float u = 0.7978845608028654f * fmaf(0.044715f * x, x * x, x);
    float t;
    asm("tanh.approx.f32 %0, %1;" : "=f"(t) : "f"(u));
    return 0.5f * x * (1.0f + t);
}
__device__ __forceinline__ uint32_t smem_to_u32(const void* p) {
    uint32_t a;
    asm("{ .reg .u64 t; cvta.to.shared.u64 t, %1; cvt.u32.u64 %0, t; }" : "=r"(a) : "l"(p));
    return a;
}
__device__ __forceinline__ void cp16(uint32_t s, const void* g) {
    asm volatile("cp.async.cg.shared.global [%0], [%1], 16;" :: "r"(s), "l"(g));
}
__device__ __forceinline__ void ldsm4(uint32_t& r0, uint32_t& r1, uint32_t& r2,
                                      uint32_t& r3, uint32_t addr) {
    asm volatile("ldmatrix.sync.aligned.m8n8.x4.shared.b16 {%0,%1,%2,%3}, [%4];"
                 : "=r"(r0), "=r"(r1), "=r"(r2), "=r"(r3) : "r"(addr));
}
__device__ __forceinline__ void mma_h(uint32_t* d, const uint32_t* a,
                                      uint32_t b0, uint32_t b1) {
    asm volatile(
        "mma.sync.aligned.m16n8k16.row.col.f16.f16.f16.f16 "
        "{%0,%1}, {%2,%3,%4,%5}, {%6,%7}, {%0,%1};"
        : "+r"(d[0]), "+r"(d[1])
        : "r"(a[0]), "r"(a[1]), "r"(a[2]), "r"(a[3]), "r"(b0), "r"(b1));
}

// smem layout for ntm_main (bytes); padded rows: 72 fp16 = 144B; 2-stage, 2 CTAs/SM
#define ROW_B 144
#define ABUF 18432
#define BBUF 36864
#define B_REG 36864
#define BASE_OFF 110592
#define W2S_OFF 111616
#define SMEM_MAIN 112640

// grid partition for k_prep
#define PREP_CONV 8192
#define PREP_W1T 1024
#define PREP_BASE 2048
#define PREP_ROWS 64
#define PREP_GRID (PREP_CONV + PREP_W1T + PREP_BASE + PREP_ROWS)

// ---------------- fused prep: conv | w1t | base | rows (all independent) ----------------
__global__ __launch_bounds__(256) void k_prep(
    const float* __restrict__ keys, const float* __restrict__ q,
    const float* __restrict__ W1,
    const float* __restrict__ nulla, const float* __restrict__ newa) {
    const int bid = blockIdx.x;
    const int t = threadIdx.x;

    if (bid < PREP_CONV) {
        // ---- keys fp32 -> fp16 ----
        size_t stride = (size_t)PREP_CONV * 256 * 4;
        for (size_t i = ((size_t)bid * 256 + t) * 4;
             i < (size_t)M_ROWS * H_DIM; i += stride) {
            float4 f = *reinterpret_cast<const float4*>(keys + i);
            uint2 o;
            o.x = pack2h(f.x, f.y);
            o.y = pack2h(f.z, f.w);
            *reinterpret_cast<uint2*>(reinterpret_cast<char*>(g_keys) + i * 2) = o;
        }
    } else if (bid < PREP_CONV + PREP_W1T) {
        // ---- W1_bot^T -> fp16 (transpose) ----
        __shared__ float tile[32][33];
        int bi = bid - PREP_CONV;
        int kb = (bi & 31) * 32, nb = (bi >> 5) * 32;
        int tx = t & 31, ty = t >> 5;
#pragma unroll
        for (int i = 0; i < 4; ++i) {
            int kl = ty + i * 8;
            tile[kl][tx] = W1[(size_t)(H_DIM + kb + kl) * H_DIM + nb + tx];
        }
        __syncthreads();
#pragma unroll
        for (int i = 0; i < 4; ++i) {
            int nl = ty + i * 8;
            g_W1T[(size_t)(nb + nl) * H_DIM + kb + tx] = __float2half(tile[tx][nl]);
        }
    } else if (bid < PREP_CONV + PREP_W1T + PREP_BASE) {
        // ---- k-split partials of q @ W1_top ----
        __shared__ float qs[8 * 128];
        int bi = bid - PREP_CONV - PREP_W1T;
        int n0 = (bi & 15) * 64, b0 = ((bi >> 4) & 15) * 8, kz = bi >> 8;
        int k0 = kz * 128;
        {
            int r = t >> 5, c = t & 31;
            *reinterpret_cast<float4*>(qs + r * 128 + c * 4) =
                *reinterpret_cast<const float4*>(q + (size_t)(b0 + r) * H_DIM + k0 + c * 4);
        }
        __syncthreads();
        int tn = t & 63, tb = t >> 6;
        int n = n0 + tn;
        float a0 = 0.f, a1 = 0.f;
        const float* qa = qs + tb * 128;
        const float* qb = qs + (tb + 4) * 128;
#pragma unroll 8
        for (int kk = 0; kk < 128; ++kk) {
            float w = W1[(size_t)(k0 + kk) * H_DIM + n];
            a0 = fmaf(qa[kk], w, a0);
            a1 = fmaf(qb[kk], w, a1);
        }
        float* dst = g_basep + (size_t)kz * B_DIM * H_DIM;
        dst[(size_t)(b0 + tb) * H_DIM + n] = a0;
        dst[(size_t)(b0 + tb + 4) * H_DIM + n] = a1;
    } else {
        // ---- null/new rows through W1_bot ----
        __shared__ float ns[H_DIM], ws[H_DIM];
        __shared__ float rN[256], rW[256];
        int bi = bid - PREP_CONV - PREP_W1T - PREP_BASE;
#pragma unroll
        for (int i = 0; i < 4; ++i) {
            ns[t + i * 256] = nulla[t + i * 256];
            ws[t + i * 256] = newa[t + i * 256];
        }
        __syncthreads();
        int nl = t & 15;
        int slice = t >> 4;
        int n = bi * 16 + nl;
        float an = 0.f, aw = 0.f;
#pragma unroll 4
        for (int kk = 0; kk < 64; ++kk) {
            int k = slice * 64 + kk;
            float w = W1[(size_t)(H_DIM + k) * H_DIM + n];
            an = fmaf(ns[k], w, an);
            aw = fmaf(ws[k], w, aw);
        }
        rN[t] = an; rW[t] = aw;
        __syncthreads();
        if (t < 16) {
            float a = 0.f, w = 0.f;
#pragma unroll
            for (int s = 0; s < 16; ++s) { a += rN[s * 16 + t]; w += rW[s * 16 + t]; }
            g_nullrow[bi * 16 + t] = a;
            g_newrow[bi * 16 + t] = w;
        }
    }
}

// ---------------- main fused GEMM (fp16 acc, 8 warps, 2 CTAs/SM) ----------------
// grid (4 n-quarters, 512 m-tiles), 256 threads = 8 warps (wm in {0,1}, wn in {0..3})
// warp tile 64m x 64n; K chunk 64; 2-stage cp.async; fragment double-buffering
__global__ __launch_bounds__(256, 2) void ntm_main(
    const float* __restrict__ b1, const float* __restrict__ W2) {
    extern __shared__ char smem[];
    const uint32_t su = smem_to_u32(smem);
    const int tid = threadIdx.x;
    const int wid = tid >> 5;
    const int l = tid & 31;
    const int wm = wid & 1;
    const int wn = wid >> 1;
    const int nq = blockIdx.x;
    const int m_base = blockIdx.y * 128;
    const int b = blockIdx.y >> 2;

    float* part = reinterpret_cast<float*>(smem);            // aliases A0 (epilogue only)
    float* base_sh = reinterpret_cast<float*>(smem + BASE_OFF);
    float* w2_sh = reinterpret_cast<float*>(smem + W2S_OFF);

    {
        int n = nq * 256 + tid;
        float v = b1[n];
        int off = b * H_DIM + n;
#pragma unroll
        for (int s = 0; s < 8; ++s) v += g_basep[(size_t)s * B_DIM * H_DIM + off];
        base_sh[tid] = v;
        w2_sh[tid] = W2[n];
    }

    const char* asrc = reinterpret_cast<const char*>(g_keys) + (size_t)m_base * H_DIM * 2;
    const char* bsrc = reinterpret_cast<const char*>(g_W1T) + (size_t)nq * 256 * H_DIM * 2;

    auto stage = [&](int c, int buf) {
        const char* ac = asrc + c * 128;
        const char* bc = bsrc + c * 128;
        uint32_t sa = su + buf * ABUF;
        uint32_t sb = su + B_REG + buf * BBUF;
#pragma unroll
        for (int i = 0; i < 4; ++i) {
            int idx = tid + i * 256;
            int row = idx >> 3, u = idx & 7;
            cp16(sa + row * ROW_B + u * 16, ac + (size_t)row * 2048 + u * 16);
        }
#pragma unroll
        for (int i = 0; i < 8; ++i) {
            int idx = tid + i * 256;
            int row = idx >> 3, u = idx & 7;
            cp16(sb + row * ROW_B + u * 16, bc + (size_t)row * 2048 + u * 16);
        }
        asm volatile("cp.async.commit_group;" ::: "memory");
    };

    uint32_t acc[4][8][2];
#pragma unroll
    for (int i = 0; i < 4; ++i)
#pragma unroll
        for (int j = 0; j < 8; ++j) { acc[i][j][0] = 0u; acc[i][j][1] = 0u; }

    const int aRow = wm * 64 + (l & 7) + ((l >> 3) & 1) * 8;
    const uint32_t aKoff = (uint32_t)(l >> 4) * 16;
    const int bRow = wn * 64 + ((l >> 4) & 1) * 8 + (l & 7);
    const uint32_t bKoff = (uint32_t)((l >> 3) & 1) * 16;

    stage(0, 0);

    uint32_t af[2][4][4], bf[2][4][4];

#pragma unroll 1
    for (int c = 0; c < 16; ++c) {
        asm volatile("cp.async.wait_group 0;" ::: "memory");
        __syncthreads();
        if (c < 15) stage(c + 1, (c + 1) & 1);

        const uint32_t baseA = su + (c & 1) * ABUF;
        const uint32_t baseB = su + B_REG + (c & 1) * BBUF;

#pragma unroll
        for (int mi = 0; mi < 4; ++mi) {
            uint32_t addr = baseA + (uint32_t)(aRow + mi * 16) * ROW_B + aKoff;
            ldsm4(af[0][mi][0], af[0][mi][1], af[0][mi][2], af[0][mi][3], addr);
        }
#pragma unroll
        for (int jp = 0; jp < 4; ++jp) {
            uint32_t addr = baseB + (uint32_t)(bRow + jp * 16) * ROW_B + bKoff;
            ldsm4(bf[0][jp][0], bf[0][jp][1], bf[0][jp][2], bf[0][jp][3], addr);
        }

#pragma unroll
        for (int ks = 0; ks < 4; ++ks) {
            const int cur = ks & 1;
            const int nxt = cur ^ 1;
            if (ks < 3) {
#pragma unroll
                for (int mi = 0; mi < 4; ++mi) {
                    uint32_t addr = baseA + (uint32_t)(aRow + mi * 16) * ROW_B + (ks + 1) * 32 + aKoff;
                    ldsm4(af[nxt][mi][0], af[nxt][mi][1], af[nxt][mi][2], af[nxt][mi][3], addr);
                }
#pragma unroll
                for (int jp = 0; jp < 4; ++jp) {
                    uint32_t addr = baseB + (uint32_t)(bRow + jp * 16) * ROW_B + (ks + 1) * 32 + bKoff;
                    ldsm4(bf[nxt][jp][0], bf[nxt][jp][1], bf[nxt][jp][2], bf[nxt][jp][3], addr);
                }
            }
#pragma unroll
            for (int mi = 0; mi < 4; ++mi)
#pragma unroll
                for (int j = 0; j < 8; ++j)
                    mma_h(acc[mi][j], af[cur][mi],
                          bf[cur][j >> 1][(j & 1) * 2], bf[cur][j >> 1][(j & 1) * 2 + 1]);
        }
    }

    float s[4][2];
#pragma unroll
    for (int mi = 0; mi < 4; ++mi) { s[mi][0] = 0.f; s[mi][1] = 0.f; }
#pragma unroll
    for (int mi = 0; mi < 4; ++mi) {
#pragma unroll
        for (int j = 0; j < 8; ++j) {
            int nb = wn * 64 + j * 8 + (l & 3) * 2;
            float w0 = w2_sh[nb], w1 = w2_sh[nb + 1];
            float bb0 = base_sh[nb], bb1 = base_sh[nb + 1];
            float2 v01 = __half22float2(reinterpret_cast<__half2&>(acc[mi][j][0]));
            float2 v23 = __half22float2(reinterpret_cast<__half2&>(acc[mi][j][1]));
            s[mi][0] += gelu_fast(v01.x + bb0) * w0 + gelu_fast(v01.y + bb1) * w1;
            s[mi][1] += gelu_fast(v23.x + bb0) * w0 + gelu_fast(v23.y + bb1) * w1;
        }
    }
    __syncthreads();
#pragma unroll
    for (int mi = 0; mi < 4; ++mi) {
#pragma unroll
        for (int h = 0; h < 2; ++h) {
            float v = s[mi][h];
            v += __shfl_xor_sync(0xffffffffu, v, 1);
            v += __shfl_xor_sync(0xffffffffu, v, 2);
            if ((l & 3) == 0) {
                int row = wm * 64 + mi * 16 + (l >> 2) + h * 8;
                part[wn * 128 + row] = v;
            }
        }
    }
    __syncthreads();
    if (tid < 128) {
        float v = part[tid] + part[128 + tid] + part[256 + tid] + part[384 + tid];
        g_partial[(size_t)nq * M_ROWS + m_base + tid] = v;
    }
}

// ---------------- fused finish: null/new scores | combine+mask ----------------
// blocks [0,128): null/new for batch b (512 thr); [128,256): combine for batch b-128
__global__ __launch_bounds__(512) void k_final(
    const float* __restrict__ b1, const float* __restrict__ W2,
    const float* __restrict__ b2, const float* __restrict__ ms,
    const int* __restrict__ es, float* __restrict__ out) {
    int t = threadIdx.x;
    if (blockIdx.x < B_DIM) {
        __shared__ float sN[512], sW[512];
        int b = blockIdx.x;
        float aN = 0.f, aW = 0.f;
#pragma unroll
        for (int rep = 0; rep < 2; ++rep) {
            int n = t + rep * 512;
            float bb = b1[n];
            int off = b * H_DIM + n;
#pragma unroll
            for (int s = 0; s < 8; ++s) bb += g_basep[(size_t)s * B_DIM * H_DIM + off];
            float w2 = W2[n];
            aN += gelu_exact(bb + g_nullrow[n]) * w2;
            aW += gelu_exact(bb + g_newrow[n]) * w2;
        }
        sN[t] = aN; sW[t] = aW;
        __syncthreads();
        for (int s = 256; s > 0; s >>= 1) {
            if (t < s) { sN[t] += sN[t + s]; sW[t] += sW[t + s]; }
            __syncthreads();
        }
        if (t == 0) {
            float bias = b2[0], m = ms[b];
            out[(size_t)b * S_DIM + 0]   = sN[0] + bias - m;
            out[(size_t)b * S_DIM + 513] = sW[0] + bias + m;
        }
    } else {
        int b = blockIdx.x - B_DIM;
        int e = t;
        size_t m = (size_t)b * E_DIM + e;
        float v = g_partial[m] + g_partial[M_ROWS + m] + g_partial[2 * (size_t)M_ROWS + m] +
                  g_partial[3 * (size_t)M_ROWS + m] + b2[0] + ms[b];
        if (e >= es[b]) v += NEG_V;
        out[(size_t)b * S_DIM + 1 + e] = v;
    }
}

// ---------------- launch ----------------
extern "C" void kernel_launch(void* const* d_in, const int* in_sizes, int n_in,
                              void* d_out, int out_size) {
    const float* query = (const float*)d_in[0];
    const float* keys  = (const float*)d_in[1];
    const int*   esz   = (const int*)d_in[2];
    const float* msc   = (const float*)d_in[3];
    const float* W1    = (const float*)d_in[4];
    const float* b1    = (const float*)d_in[5];
    const float* W2    = (const float*)d_in[6];
    const float* b2    = (const float*)d_in[7];
    const float* nulla = (const float*)d_in[8];
    const float* newa  = (const float*)d_in[9];
    float* out = (float*)d_out;

    cudaFuncSetAttribute(ntm_main, cudaFuncAttributeMaxDynamicSharedMemorySize, SMEM_MAIN);

    k_prep<<<PREP_GRID, 256>>>(keys, query, W1, nulla, newa);
    ntm_main<<<dim3(4, 512), 256, SMEM_MAIN>>>(b1, W2);
    k_final<<<2 * B_DIM, 512>>>(b1, W2, b2, msc, esz, out);
}

// round 15
// speedup vs baseline: 1.0016x; 1.0016x over previous
#include <cuda_runtime.h>
#include <cuda_fp16.h>
#include <cstdint>

#define B_DIM 128
#define E_DIM 512
#define H_DIM 1024
#define S_DIM 514
#define M_ROWS 65536
#define NEG_V (-1000000.0f)

// ---------------- device scratch ----------------
__device__ __half g_keys[(size_t)M_ROWS * H_DIM];  // keys in fp16
__device__ __half g_W1T[H_DIM * H_DIM];            // W1_bot^T [n][k] fp16
__device__ float g_basep[8 * B_DIM * H_DIM];       // k-split partials of q@W1_top
__device__ float g_nullrow[H_DIM];
__device__ float g_newrow[H_DIM];
__device__ float g_partial[4 * M_ROWS];

// ---------------- helpers ----------------
__device__ __forceinline__ uint32_t pack2h(float a, float b) {
    __half2 h = __floats2half2_rn(a, b);
    return reinterpret_cast<uint32_t&>(h);
}
__device__ __forceinline__ float gelu_exact(float x) {
    return 0.5f * x * (1.0f + erff(x * 0.70710678118654752f));
}
__device__ __forceinline__ float gelu_fast(float x) {
    float u = 0.7978845608028654f * fmaf(0.044715f * x, x * x, x);
    float t;
    asm("tanh.approx.f32 %0, %1;" : "=f"(t) : "f"(u));
    return 0.5f * x * (1.0f + t);
}
__device__ __forceinline__ uint32_t smem_to_u32(const void* p) {
    uint32_t a;
    asm("{ .reg .u64 t; cvta.to.shared.u64 t, %1; cvt.u32.u64 %0, t; }" : "=r"(a) : "l"(p));
    return a;
}
__device__ __forceinline__ void cp16(uint32_t s, const void* g) {
    asm volatile("cp.async.cg.shared.global [%0], [%1], 16;" :: "r"(s), "l"(g));
}
__device__ __forceinline__ void ldsm4(uint32_t& r0, uint32_t& r1, uint32_t& r2,
                                      uint32_t& r3, uint32_t addr) {
    asm volatile("ldmatrix.sync.aligned.m8n8.x4.shared.b16 {%0,%1,%2,%3}, [%4];"
                 : "=r"(r0), "=r"(r1), "=r"(r2), "=r"(r3) : "r"(addr));
}
__device__ __forceinline__ void mma_h(uint32_t* d, const uint32_t* a,
                                      uint32_t b0, uint32_t b1) {
    asm volatile(
        "mma.sync.aligned.m16n8k16.row.col.f16.f16.f16.f16 "
        "{%0,%1}, {%2,%3,%4,%5}, {%6,%7}, {%0,%1};"
        : "+r"(d[0]), "+r"(d[1])
        : "r"(a[0]), "r"(a[1]), "r"(a[2]), "r"(a[3]), "r"(b0), "r"(b1));
}

// smem layout for ntm_main (bytes); padded rows: 72 fp16 = 144B; 2-stage, 2 CTAs/SM
#define ROW_B 144
#define ABUF 18432
#define BBUF 36864
#define B_REG 36864
#define BASE_OFF 110592
#define W2S_OFF 111616
#define SMEM_MAIN 112640

// grid partition for k_prep
#define PREP_CONV 8192
#define PREP_W1T 1024
#define PREP_BASE 2048
#define PREP_ROWS 64
#define PREP_GRID (PREP_CONV + PREP_W1T + PREP_BASE + PREP_ROWS)

// ---------------- fused prep: conv | w1t | base | rows (all independent) ----------------
__global__ __launch_bounds__(256) void k_prep(
    const float* __restrict__ keys, const float* __restrict__ q,
    const float* __restrict__ W1,
    const float* __restrict__ nulla, const float* __restrict__ newa) {
    const int bid = blockIdx.x;
    const int t = threadIdx.x;

    if (bid < PREP_CONV) {
        // ---- keys fp32 -> fp16 ----
        size_t stride = (size_t)PREP_CONV * 256 * 4;
        for (size_t i = ((size_t)bid * 256 + t) * 4;
             i < (size_t)M_ROWS * H_DIM; i += stride) {
            float4 f = *reinterpret_cast<const float4*>(keys + i);
            uint2 o;
            o.x = pack2h(f.x, f.y);
            o.y = pack2h(f.z, f.w);
            *reinterpret_cast<uint2*>(reinterpret_cast<char*>(g_keys) + i * 2) = o;
        }
    } else if (bid < PREP_CONV + PREP_W1T) {
        // ---- W1_bot^T -> fp16 (transpose) ----
        __shared__ float tile[32][33];
        int bi = bid - PREP_CONV;
        int kb = (bi & 31) * 32, nb = (bi >> 5) * 32;
        int tx = t & 31, ty = t >> 5;
#pragma unroll
        for (int i = 0; i < 4; ++i) {
            int kl = ty + i * 8;
            tile[kl][tx] = W1[(size_t)(H_DIM + kb + kl) * H_DIM + nb + tx];
        }
        __syncthreads();
#pragma unroll
        for (int i = 0; i < 4; ++i) {
            int nl = ty + i * 8;
            g_W1T[(size_t)(nb + nl) * H_DIM + kb + tx] = __float2half(tile[tx][nl]);
        }
    } else if (bid < PREP_CONV + PREP_W1T + PREP_BASE) {
        // ---- k-split partials of q @ W1_top ----
        __shared__ float qs[8 * 128];
        int bi = bid - PREP_CONV - PREP_W1T;
        int n0 = (bi & 15) * 64, b0 = ((bi >> 4) & 15) * 8, kz = bi >> 8;
        int k0 = kz * 128;
        {
            int r = t >> 5, c = t & 31;
            *reinterpret_cast<float4*>(qs + r * 128 + c * 4) =
                *reinterpret_cast<const float4*>(q + (size_t)(b0 + r) * H_DIM + k0 + c * 4);
        }
        __syncthreads();
        int tn = t & 63, tb = t >> 6;
        int n = n0 + tn;
        float a0 = 0.f, a1 = 0.f;
        const float* qa = qs + tb * 128;
        const float* qb = qs + (tb + 4) * 128;
#pragma unroll 8
        for (int kk = 0; kk < 128; ++kk) {
            float w = W1[(size_t)(k0 + kk) * H_DIM + n];
            a0 = fmaf(qa[kk], w, a0);
            a1 = fmaf(qb[kk], w, a1);
        }
        float* dst = g_basep + (size_t)kz * B_DIM * H_DIM;
        dst[(size_t)(b0 + tb) * H_DIM + n] = a0;
        dst[(size_t)(b0 + tb + 4) * H_DIM + n] = a1;
    } else {
        // ---- null/new rows through W1_bot ----
        __shared__ float ns[H_DIM], ws[H_DIM];
        __shared__ float rN[256], rW[256];
        int bi = bid - PREP_CONV - PREP_W1T - PREP_BASE;
#pragma unroll
        for (int i = 0; i < 4; ++i) {
            ns[t + i * 256] = nulla[t + i * 256];
            ws[t + i * 256] = newa[t + i * 256];
        }
        __syncthreads();
        int nl = t & 15;
        int slice = t >> 4;
        int n = bi * 16 + nl;
        float an = 0.f, aw = 0.f;
#pragma unroll 4
        for (int kk = 0; kk < 64; ++kk) {
            int k = slice * 64 + kk;
            float w = W1[(size_t)(H_DIM + k) * H_DIM + n];
            an = fmaf(ns[k], w, an);
            aw = fmaf(ws[k], w, aw);
        }
        rN[t] = an; rW[t] = aw;
        __syncthreads();
        if (t < 16) {
            float a = 0.f, w = 0.f;
#pragma unroll
            for (int s = 0; s < 16; ++s) { a += rN[s * 16 + t]; w += rW[s * 16 + t]; }
            g_nullrow[bi * 16 + t] = a;
            g_newrow[bi * 16 + t] = w;
        }
    }
}

// ---------------- main fused GEMM (fp16 acc, 8 warps, 2 CTAs/SM) ----------------
// grid (4 n-quarters, 512 m-tiles), 256 threads = 8 warps (wm in {0,1}, wn in {0..3})
// warp tile 64m x 64n; K chunk 64; 2-stage cp.async; fragment double-buffering
__global__ __launch_bounds__(256, 2) void ntm_main(
    const float* __restrict__ b1, const float* __restrict__ W2) {
    extern __shared__ char smem[];
    const uint32_t su = smem_to_u32(smem);
    const int tid = threadIdx.x;
    const int wid = tid >> 5;
    const int l = tid & 31;
    const int wm = wid & 1;
    const int wn = wid >> 1;
    const int nq = blockIdx.x;
    const int m_base = blockIdx.y * 128;
    const int b = blockIdx.y >> 2;

    float* part = reinterpret_cast<float*>(smem);            // aliases A0 (epilogue only)
    float* base_sh = reinterpret_cast<float*>(smem + BASE_OFF);
    float* w2_sh = reinterpret_cast<float*>(smem + W2S_OFF);

    {
        int n = nq * 256 + tid;
        float v = b1[n];
        int off = b * H_DIM + n;
#pragma unroll
        for (int s = 0; s < 8; ++s) v += g_basep[(size_t)s * B_DIM * H_DIM + off];
        base_sh[tid] = v;
        w2_sh[tid] = W2[n];
    }

    const char* asrc = reinterpret_cast<const char*>(g_keys) + (size_t)m_base * H_DIM * 2;
    const char* bsrc = reinterpret_cast<const char*>(g_W1T) + (size_t)nq * 256 * H_DIM * 2;

    auto stage = [&](int c, int buf) {
        const char* ac = asrc + c * 128;
        const char* bc = bsrc + c * 128;
        uint32_t sa = su + buf * ABUF;
        uint32_t sb = su + B_REG + buf * BBUF;
#pragma unroll
        for (int i = 0; i < 4; ++i) {
            int idx = tid + i * 256;
            int row = idx >> 3, u = idx & 7;
            cp16(sa + row * ROW_B + u * 16, ac + (size_t)row * 2048 + u * 16);
        }
#pragma unroll
        for (int i = 0; i < 8; ++i) {
            int idx = tid + i * 256;
            int row = idx >> 3, u = idx & 7;
            cp16(sb + row * ROW_B + u * 16, bc + (size_t)row * 2048 + u * 16);
        }
        asm volatile("cp.async.commit_group;" ::: "memory");
    };

    uint32_t acc[4][8][2];
#pragma unroll
    for (int i = 0; i < 4; ++i)
#pragma unroll
        for (int j = 0; j < 8; ++j) { acc[i][j][0] = 0u; acc[i][j][1] = 0u; }

    const int aRow = wm * 64 + (l & 7) + ((l >> 3) & 1) * 8;
    const uint32_t aKoff = (uint32_t)(l >> 4) * 16;
    const int bRow = wn * 64 + ((l >> 4) & 1) * 8 + (l & 7);
    const uint32_t bKoff = (uint32_t)((l >> 3) & 1) * 16;

    stage(0, 0);

    uint32_t af[2][4][4], bf[2][4][4];

#pragma unroll 1
    for (int c = 0; c < 16; ++c) {
        asm volatile("cp.async.wait_group 0;" ::: "memory");
        __syncthreads();
        if (c < 15) stage(c + 1, (c + 1) & 1);

        const uint32_t baseA = su + (c & 1) * ABUF;
        const uint32_t baseB = su + B_REG + (c & 1) * BBUF;

#pragma unroll
        for (int mi = 0; mi < 4; ++mi) {
            uint32_t addr = baseA + (uint32_t)(aRow + mi * 16) * ROW_B + aKoff;
            ldsm4(af[0][mi][0], af[0][mi][1], af[0][mi][2], af[0][mi][3], addr);
        }
#pragma unroll
        for (int jp = 0; jp < 4; ++jp) {
            uint32_t addr = baseB + (uint32_t)(bRow + jp * 16) * ROW_B + bKoff;
            ldsm4(bf[0][jp][0], bf[0][jp][1], bf[0][jp][2], bf[0][jp][3], addr);
        }

#pragma unroll
        for (int ks = 0; ks < 4; ++ks) {
            const int cur = ks & 1;
            const int nxt = cur ^ 1;
            if (ks < 3) {
#pragma unroll
                for (int mi = 0; mi < 4; ++mi) {
                    uint32_t addr = baseA + (uint32_t)(aRow + mi * 16) * ROW_B + (ks + 1) * 32 + aKoff;
                    ldsm4(af[nxt][mi][0], af[nxt][mi][1], af[nxt][mi][2], af[nxt][mi][3], addr);
                }
#pragma unroll
                for (int jp = 0; jp < 4; ++jp) {
                    uint32_t addr = baseB + (uint32_t)(bRow + jp * 16) * ROW_B + (ks + 1) * 32 + bKoff;
                    ldsm4(bf[nxt][jp][0], bf[nxt][jp][1], bf[nxt][jp][2], bf[nxt][jp][3], addr);
                }
            }
#pragma unroll
            for (int mi = 0; mi < 4; ++mi)
#pragma unroll
                for (int j = 0; j < 8; ++j)
                    mma_h(acc[mi][j], af[cur][mi],
                          bf[cur][j >> 1][(j & 1) * 2], bf[cur][j >> 1][(j & 1) * 2 + 1]);
        }
    }

    float s[4][2];
#pragma unroll
    for (int mi = 0; mi < 4; ++mi) { s[mi][0] = 0.f; s[mi][1] = 0.f; }
#pragma unroll
    for (int mi = 0; mi < 4; ++mi) {
#pragma unroll
        for (int j = 0; j < 8; ++j) {
            int nb = wn * 64 + j * 8 + (l & 3) * 2;
            float w0 = w2_sh[nb], w1 = w2_sh[nb + 1];
            float bb0 = base_sh[nb], bb1 = base_sh[nb + 1];
            float2 v01 = __half22float2(reinterpret_cast<__half2&>(acc[mi][j][0]));
            float2 v23 = __half22float2(reinterpret_cast<__half2&>(acc[mi][j][1]));
            s[mi][0] += gelu_fast(v01.x + bb0) * w0 + gelu_fast(v01.y + bb1) * w1;
            s[mi][1] += gelu_fast(v23.x + bb0) * w0 + gelu_fast(v23.y + bb1) * w1;
        }
    }
    __syncthreads();
#pragma unroll
    for (int mi = 0; mi < 4; ++mi) {
#pragma unroll
        for (int h = 0; h < 2; ++h) {
            float v = s[mi][h];
            v += __shfl_xor_sync(0xffffffffu, v, 1);
            v += __shfl_xor_sync(0xffffffffu, v, 2);
            if ((l & 3) == 0) {
                int row = wm * 64 + mi * 16 + (l >> 2) + h * 8;
                part[wn * 128 + row] = v;
            }
        }
    }
    __syncthreads();
    if (tid < 128) {
        float v = part[tid] + part[128 + tid] + part[256 + tid] + part[384 + tid];
        g_partial[(size_t)nq * M_ROWS + m_base + tid] = v;
    }
}

// ---------------- fused finish: null/new scores | combine+mask ----------------
// blocks [0,128): null/new for batch b (512 thr); [128,256): combine for batch b-128
__global__ __launch_bounds__(512) void k_final(
    const float* __restrict__ b1, const float* __restrict__ W2,
    const float* __restrict__ b2, const float* __restrict__ ms,
    const int* __restrict__ es, float* __restrict__ out) {
    int t = threadIdx.x;
    if (blockIdx.x < B_DIM) {
        __shared__ float sN[512], sW[512];
        int b = blockIdx.x;
        float aN = 0.f, aW = 0.f;
#pragma unroll
        for (int rep = 0; rep < 2; ++rep) {
            int n = t + rep * 512;
            float bb = b1[n];
            int off = b * H_DIM + n;
#pragma unroll
            for (int s = 0; s < 8; ++s) bb += g_basep[(size_t)s * B_DIM * H_DIM + off];
            float w2 = W2[n];
            aN += gelu_exact(bb + g_nullrow[n]) * w2;
            aW += gelu_exact(bb + g_newrow[n]) * w2;
        }
        sN[t] = aN; sW[t] = aW;
        __syncthreads();
        for (int s = 256; s > 0; s >>= 1) {
            if (t < s) { sN[t] += sN[t + s]; sW[t] += sW[t + s]; }
            __syncthreads();
        }
        if (t == 0) {
            float bias = b2[0], m = ms[b];
            out[(size_t)b * S_DIM + 0]   = sN[0] + bias - m;
            out[(size_t)b * S_DIM + 513] = sW[0] + bias + m;
        }
    } else {
        int b = blockIdx.x - B_DIM;
        int e = t;
        size_t m = (size_t)b * E_DIM + e;
        float v = g_partial[m] + g_partial[M_ROWS + m] + g_partial[2 * (size_t)M_ROWS + m] +
                  g_partial[3 * (size_t)M_ROWS + m] + b2[0] + ms[b];
        if (e >= es[b]) v += NEG_V;
        out[(size_t)b * S_DIM + 1 + e] = v;
    }
}

// ---------------- launch ----------------
extern "C" void kernel_launch(void* const* d_in, const int* in_sizes, int n_in,
                              void* d_out, int out_size) {
    const float* query = (const float*)d_in[0];
    const float* keys  = (const float*)d_in[1];
    const int*   esz   = (const int*)d_in[2];
    const float* msc   = (const float*)d_in[3];
    const float* W1    = (const float*)d_in[4];
    const float* b1    = (const float*)d_in[5];
    const float* W2    = (const float*)d_in[6];
    const float* b2    = (const float*)d_in[7];
    const float* nulla = (const float*)d_in[8];
    const float* newa  = (const float*)d_in[9];
    float* out = (float*)d_out;

    cudaFuncSetAttribute(ntm_main, cudaFuncAttributeMaxDynamicSharedMemorySize, SMEM_MAIN);

    k_prep<<<PREP_GRID, 256>>>(keys, query, W1, nulla, newa);
    ntm_main<<<dim3(4, 512), 256, SMEM_MAIN>>>(b1, W2);
    k_final<<<2 * B_DIM, 512>>>(b1, W2, b2, msc, esz, out);
}